// round 7
// baseline (speedup 1.0000x reference)
#include <cuda_runtime.h>
#include <math.h>

#define TQ 64
#define IQ 9
#define NQ 128
#define VQ 20
#define CQ 100
#define OQ 8
#define GQ 4
#define BLK 128
#define EPSQ 1e-8f
#define PBLK 96
#define HTS 128   // h_t / WfT row stride: 120 valid ([h|r]) + 8 zero pad

// p_s per-g block (96 floats, base g*96), all vector-aligned:
//  0..19 kr | 20..22 sr, 23 gammar | 24 betar, 25 gr, 26 betaw, 27 gw
//  28..30 sw, 31 gammaw | 32..51 kw | 52..71 e | 72..91 a | 92..95 pad

// ---- transposed-weight scratch (one-time prep kernel fills these) ----
__device__ __align__(16) float WcT_g[CQ * 32];        // [tid][j0..31]  (29 valid, pad 0)
__device__ __align__(16) float WrT_g[26 * CQ];        // [cc][j0..99]
__device__ __align__(16) float WwT_g[66 * CQ];        // [cc][j0..99]
__device__ __align__(16) float WfT_g[OQ * HTS];       // [o][j0..127]   (120 valid, pad 0)

__global__ void prep_kernel(const float* __restrict__ Wc, const float* __restrict__ Wr,
                            const float* __restrict__ Ww, const float* __restrict__ Wf) {
    int i = blockIdx.x * blockDim.x + threadIdx.x;
    if (i < CQ * 32) {
        int r = i >> 5, c = i & 31;
        WcT_g[i] = (c < 29) ? Wc[c * CQ + r] : 0.f;
    }
    int j = i - CQ * 32;
    if (j >= 0 && j < 26 * CQ) {
        int r = j / CQ, c = j - r * CQ;
        WrT_g[j] = Wr[c * 26 + r];
    }
    int k = i - CQ * 32 - 26 * CQ;
    if (k >= 0 && k < 66 * CQ) {
        int r = k / CQ, c = k - r * CQ;
        WwT_g[k] = Ww[c * 66 + r];
    }
    int l = i - CQ * 32 - 26 * CQ - 66 * CQ;
    if (l >= 0 && l < OQ * HTS) {
        int r = l / HTS, c = l - r * HTS;
        WfT_g[l] = (c < 120) ? Wf[c * OQ + r] : 0.f;
    }
}

__device__ __forceinline__ float ftanh_(float x) {
    float xc = fminf(fmaxf(x, -15.f), 15.f);
    float e = __expf(2.f * xc);
    return __fdividef(e - 1.f, e + 1.f);
}
__device__ __forceinline__ float fsoftplus_(float x) {
    return fmaxf(x, 0.f) + __logf(1.f + __expf(-fabsf(x)));
}
__device__ __forceinline__ float fsigmoid_(float x) {
    return __fdividef(1.f, 1.f + __expf(-x));
}
__device__ __forceinline__ float apply_act(int at, float v) {
    switch (at) {
        case 0:  return ftanh_(v);
        case 1:  return fsoftplus_(v);
        case 2:  return fsigmoid_(v);
        case 3:  return __expf(v);
        default: return 1.f + fsoftplus_(v);
    }
}
__device__ __forceinline__ float warp_sum(float v) {
    v += __shfl_xor_sync(0xffffffffu, v, 16);
    v += __shfl_xor_sync(0xffffffffu, v, 8);
    v += __shfl_xor_sync(0xffffffffu, v, 4);
    v += __shfl_xor_sync(0xffffffffu, v, 2);
    v += __shfl_xor_sync(0xffffffffu, v, 1);
    return v;
}

__global__ __launch_bounds__(BLK, 4) void ntm_kernel(
    const float* __restrict__ x,
    const float* __restrict__ bc, const float* __restrict__ br,
    const float* __restrict__ bw, const float* __restrict__ bf,
    const float* __restrict__ r_bias, const float* __restrict__ M_bias,
    float* __restrict__ out)
{
    extern __shared__ float sm[];
    float* M_s     = sm;                    // [G][128][20]  10240 (80B rows)
    float* wr_s    = M_s + GQ * NQ * VQ;    // [G][128]  er (unnormalized)
    float* ew_s    = wr_s + GQ * NQ;        // [G][128]  ew (unnormalized)
    float* wpr_s   = ew_s + GQ * NQ;        // [G][128]  wpr (pre-norm read weights)
    float* wprev_s = wpr_s + GQ * NQ;       // [G][128]  normalized w_w (prev step)
    float* z_s     = wprev_s + GQ * NQ;     // [32][G]   controller input (x|r)
    float* h_s     = z_s + 32 * GQ;         // [100][G]  controller hidden
    float* h_t     = h_s + CQ * GQ;         // [G][128]  [h(100)|r(20)|0pad(8)]
    float* p_s     = h_t + GQ * HTS;        // [G][96]   head params
    float* red     = p_s + GQ * PBLK;       // [3][16]   block-reduce partials

    const int tid  = threadIdx.x;
    const int lane = tid & 31;
    const int warp = tid >> 5;
    const int n    = tid;
    const int nm1  = (n - 1) & 127, np1 = (n + 1) & 127;
    const int b0   = blockIdx.x * GQ;

    // ---- hoisted per-thread constants ----
    float bcv = (tid < CQ) ? bc[tid] : 0.f;
    const float* WpT = WwT_g; int st = 0, at = 0; float bsv = 0.f;
    {
        bool rh = (tid < 26);
        int c = rh ? tid : tid - 26;
        if (rh)            { WpT = WrT_g + c * CQ; bsv = br[c]; }
        else if (tid < 92) { WpT = WwT_g + c * CQ; bsv = bw[c]; }
        if      (c < 20)  { st = (rh ? 0 : 32) + c;       at = 0; }
        else if (c == 20) { st = rh ? 24 : 26;            at = 1; }
        else if (c == 21) { st = rh ? 25 : 27;            at = 2; }
        else if (c < 25)  { st = (rh ? 20 : 28) + (c-22); at = 3; }
        else if (c == 25) { st = rh ? 23 : 31;            at = 4; }
        else if (c < 46)  { st = 52 + (c - 26);           at = 2; }
        else              { st = 72 + (c - 46);           at = 0; }
    }
    float bfv = bf[lane & 7];

    // ---- init state ----
    float wprev_r[GQ], wpw_r[GQ];
    {
        float4 mb[5];
        const float4* Mb = (const float4*)M_bias;   // [128][5]
        #pragma unroll
        for (int i = 0; i < 5; i++) mb[i] = Mb[n * 5 + i];
        #pragma unroll
        for (int g = 0; g < GQ; g++) {
            wprev_r[g] = 0.f;
            wprev_s[g * NQ + n] = 0.f;
            float4* Mr = (float4*)&M_s[(g * NQ + n) * VQ];
            #pragma unroll
            for (int i = 0; i < 5; i++) Mr[i] = mb[i];
        }
    }
    if (tid < VQ * GQ) {                    // r0
        int g = tid & 3, v = tid >> 2;
        z_s[(IQ + v) * GQ + g] = r_bias[v];
    }
    if (tid < IQ * GQ) {                    // x_0
        int g = tid / IQ, i = tid - g * IQ;
        z_s[i * GQ + g] = x[(b0 + g) * TQ * IQ + i];
    }
    if (tid < 12) {                         // zero pads: z_s j=29..31
        int j = 29 + (tid >> 2), g = tid & 3;
        z_s[j * GQ + g] = 0.f;
    }
    if (tid < 32) {                         // zero pads: h_t[g][120..127]
        int g = tid >> 3;
        h_t[g * HTS + 120 + (tid & 7)] = 0.f;
    }
    __syncthreads();

    for (int t = 0; t < TQ; t++) {
        // ---- P1: controller h = tanh([x,r] @ Wc + bc) ----
        if (tid < CQ) {
            const float4* wrow = (const float4*)(WcT_g + tid * 32);   // 8 float4
            const float4* z4   = (const float4*)z_s;                  // z4[j] = z_s[j][0..3]
            float a0 = bcv, a1 = bcv, a2 = bcv, a3 = bcv;
            #pragma unroll
            for (int jb = 0; jb < 8; jb++) {
                float4 w  = wrow[jb];
                float4 zx = z4[4 * jb + 0], zy = z4[4 * jb + 1];
                float4 zz = z4[4 * jb + 2], zw = z4[4 * jb + 3];
                a0 = fmaf(w.x, zx.x, a0); a1 = fmaf(w.x, zx.y, a1);
                a2 = fmaf(w.x, zx.z, a2); a3 = fmaf(w.x, zx.w, a3);
                a0 = fmaf(w.y, zy.x, a0); a1 = fmaf(w.y, zy.y, a1);
                a2 = fmaf(w.y, zy.z, a2); a3 = fmaf(w.y, zy.w, a3);
                a0 = fmaf(w.z, zz.x, a0); a1 = fmaf(w.z, zz.y, a1);
                a2 = fmaf(w.z, zz.z, a2); a3 = fmaf(w.z, zz.w, a3);
                a0 = fmaf(w.w, zw.x, a0); a1 = fmaf(w.w, zw.y, a1);
                a2 = fmaf(w.w, zw.z, a2); a3 = fmaf(w.w, zw.w, a3);
            }
            float h0 = ftanh_(a0), h1 = ftanh_(a1), h2 = ftanh_(a2), h3 = ftanh_(a3);
            *(float4*)&h_s[tid * GQ] = make_float4(h0, h1, h2, h3);
            h_t[0 * HTS + tid] = h0; h_t[1 * HTS + tid] = h1;
            h_t[2 * HTS + tid] = h2; h_t[3 * HTS + tid] = h3;
        }
        __syncthreads();

        // ---- P2: head matvecs (transposed weights) + fused activations ----
        if (tid < 92) {
            const float4* wrow = (const float4*)WpT;                  // 25 float4
            const float4* h4   = (const float4*)h_s;
            float a0 = bsv, a1 = bsv, a2 = bsv, a3 = bsv;
            #pragma unroll 5
            for (int jb = 0; jb < 25; jb++) {
                float4 w  = wrow[jb];
                float4 hx = h4[4 * jb + 0], hy = h4[4 * jb + 1];
                float4 hz = h4[4 * jb + 2], hw = h4[4 * jb + 3];
                a0 = fmaf(w.x, hx.x, a0); a1 = fmaf(w.x, hx.y, a1);
                a2 = fmaf(w.x, hx.z, a2); a3 = fmaf(w.x, hx.w, a3);
                a0 = fmaf(w.y, hy.x, a0); a1 = fmaf(w.y, hy.y, a1);
                a2 = fmaf(w.y, hy.z, a2); a3 = fmaf(w.y, hy.w, a3);
                a0 = fmaf(w.z, hz.x, a0); a1 = fmaf(w.z, hz.y, a1);
                a2 = fmaf(w.z, hz.z, a2); a3 = fmaf(w.z, hz.w, a3);
                a0 = fmaf(w.w, hw.x, a0); a1 = fmaf(w.w, hw.y, a1);
                a2 = fmaf(w.w, hw.z, a2); a3 = fmaf(w.w, hw.w, a3);
            }
            p_s[0 * PBLK + st] = apply_act(at, a0);
            p_s[1 * PBLK + st] = apply_act(at, a1);
            p_s[2 * PBLK + st] = apply_act(at, a2);
            p_s[3 * PBLK + st] = apply_act(at, a3);
        }
        __syncthreads();

        // ---- P5: fused content addressing, both heads ----
        #pragma unroll
        for (int g = 0; g < GQ; g++) {
            const float* pg = p_s + g * PBLK;
            float4 bv = *(const float4*)(pg + 24);      // betar, gr, betaw, gw
            const float4* Mrow = (const float4*)&M_s[(g * NQ + n) * VQ];
            const float4* krp  = (const float4*)pg;
            const float4* kwp  = (const float4*)(pg + 32);
            float dr = 0.f, dw = 0.f, n2 = 0.f, kr2 = 0.f, kw2 = 0.f;
            #pragma unroll
            for (int i = 0; i < 5; i++) {
                float4 m = Mrow[i], kr = krp[i], kw = kwp[i];
                dr = fmaf(kr.x, m.x, dr); dr = fmaf(kr.y, m.y, dr);
                dr = fmaf(kr.z, m.z, dr); dr = fmaf(kr.w, m.w, dr);
                dw = fmaf(kw.x, m.x, dw); dw = fmaf(kw.y, m.y, dw);
                dw = fmaf(kw.z, m.z, dw); dw = fmaf(kw.w, m.w, dw);
                n2 = fmaf(m.x, m.x, n2);  n2 = fmaf(m.y, m.y, n2);
                n2 = fmaf(m.z, m.z, n2);  n2 = fmaf(m.w, m.w, n2);
                kr2 = fmaf(kr.x, kr.x, kr2); kr2 = fmaf(kr.y, kr.y, kr2);
                kr2 = fmaf(kr.z, kr.z, kr2); kr2 = fmaf(kr.w, kr.w, kr2);
                kw2 = fmaf(kw.x, kw.x, kw2); kw2 = fmaf(kw.y, kw.y, kw2);
                kw2 = fmaf(kw.z, kw.z, kw2); kw2 = fmaf(kw.w, kw.w, kw2);
            }
            float mn = sqrtf(n2);
            float er  = __expf(bv.x * __fdividef(dr, sqrtf(kr2) * mn + EPSQ));
            float ewv = __expf(bv.z * __fdividef(dw, sqrtf(kw2) * mn + EPSQ));
            wr_s[g * NQ + n] = er;
            ew_s[g * NQ + n] = ewv;
            float sr = warp_sum(er), sw = warp_sum(ewv);
            if (lane == 0) { red[g * 4 + warp] = sr; red[16 + g * 4 + warp] = sw; }
        }
        // shift-softmax normalize (exp values -> probabilities), 2 heads x 4 g
        if (tid < 8) {
            int hh = tid >> 2, g = tid & 3;
            float* pg = p_s + g * PBLK;
            int sb = hh ? 28 : 20;
            float e0 = pg[sb], e1 = pg[sb + 1], e2 = pg[sb + 2];
            float inv = __fdividef(1.f, e0 + e1 + e2);
            pg[sb] = e0 * inv; pg[sb + 1] = e1 * inv; pg[sb + 2] = e2 * inv;
        }
        __syncthreads();

        // ---- P7: read-head conv + sharpen (interpolation inline) ----
        #pragma unroll
        for (int g = 0; g < GQ; g++) {
            const float* pg = p_s + g * PBLK;
            float4 sv = *(const float4*)(pg + 20);      // sr0,sr1,sr2,gammar
            float gr = pg[25];
            float se = red[g*4] + red[g*4+1] + red[g*4+2] + red[g*4+3];
            float ginv = gr * __fdividef(1.f, se);
            float omg  = 1.f - gr;
            const float* erp = &wr_s[g * NQ];
            const float* wpv = &wprev_s[g * NQ];
            float w_m = ginv * erp[nm1] + omg * wpv[nm1];
            float w_0 = ginv * erp[n]   + omg * wprev_r[g];
            float w_p = ginv * erp[np1] + omg * wpv[np1];
            float ws  = sv.x * w_p + sv.y * w_0 + sv.z * w_m;
            float wpr = __expf(sv.w * __logf(ws));
            wpr_s[g * NQ + n] = wpr;
            float sp = warp_sum(wpr);
            if (lane == 0) red[32 + g * 4 + warp] = sp;
        }
        __syncthreads();

        // ---- P9: write-head conv + sharpen (inline interp) AND r-readout ----
        #pragma unroll
        for (int g = 0; g < GQ; g++) {
            const float* pg = p_s + g * PBLK;
            float4 sv = *(const float4*)(pg + 28);      // sw0,sw1,sw2,gammaw
            float gw = pg[27];
            float sumw  = red[16 + g*4] + red[16 + g*4+1] + red[16 + g*4+2] + red[16 + g*4+3];
            float sp    = red[32 + g*4] + red[32 + g*4+1] + red[32 + g*4+2] + red[32 + g*4+3];
            float invsp = __fdividef(1.f, sp + EPSQ);
            float gwinv = gw * __fdividef(1.f, sumw);
            float omg   = 1.f - gw;
            float omgsp = omg * invsp;
            const float* wprp = &wpr_s[g * NQ];
            const float* ewp  = &ew_s[g * NQ];
            float w_m = gwinv * ewp[nm1] + omgsp * wprp[nm1];
            float w_0 = gwinv * ewp[n]   + omgsp * wprp[n];
            float w_p = gwinv * ewp[np1] + omgsp * wprp[np1];
            float ws  = sv.x * w_p + sv.y * w_0 + sv.z * w_m;
            float wpw = __expf(sv.w * __logf(ws));
            wpw_r[g] = wpw;                             // kept in regs; normalized in P10
            float s2 = warp_sum(wpw);
            if (lane == 0) red[g * 4 + warp] = s2;      // er sums dead -> reuse slot 0
        }
        // r = w_r @ M (warp-per-g), normalization factored out
        {
            int g = warp;
            float sp = red[32 + g*4] + red[32 + g*4+1] + red[32 + g*4+2] + red[32 + g*4+3];
            float invsp = __fdividef(1.f, sp + EPSQ);
            const float* wprp = &wpr_s[g * NQ];
            float w0 = wprp[lane], w1 = wprp[lane + 32], w2 = wprp[lane + 64], w3 = wprp[lane + 96];
            const float4* M0 = (const float4*)&M_s[(g * NQ + lane) * VQ];
            const float4* M1 = (const float4*)&M_s[(g * NQ + lane + 32) * VQ];
            const float4* M2 = (const float4*)&M_s[(g * NQ + lane + 64) * VQ];
            const float4* M3 = (const float4*)&M_s[(g * NQ + lane + 96) * VQ];
            #pragma unroll
            for (int vb = 0; vb < 5; vb++) {
                float4 m0 = M0[vb], m1 = M1[vb], m2 = M2[vb], m3 = M3[vb];
                float ax = w0*m0.x + w1*m1.x + w2*m2.x + w3*m3.x;
                float ay = w0*m0.y + w1*m1.y + w2*m2.y + w3*m3.y;
                float az = w0*m0.z + w1*m1.z + w2*m2.z + w3*m3.z;
                float aw = w0*m0.w + w1*m1.w + w2*m2.w + w3*m3.w;
                ax = warp_sum(ax); ay = warp_sum(ay); az = warp_sum(az); aw = warp_sum(aw);
                if (lane == 0) {
                    float4 rv = make_float4(ax * invsp, ay * invsp, az * invsp, aw * invsp);
                    *(float4*)(h_t + g * HTS + 100 + vb * 4) = rv;   // 100..119, fits in 128
                    int vbase = IQ + vb * 4;
                    z_s[(vbase + 0) * GQ + g] = rv.x;
                    z_s[(vbase + 1) * GQ + g] = rv.y;
                    z_s[(vbase + 2) * GQ + g] = rv.z;
                    z_s[(vbase + 3) * GQ + g] = rv.w;
                }
            }
        }
        __syncthreads();

        // ---- P10: normalize w_w, M update, output, x prefetch ----
        #pragma unroll
        for (int g = 0; g < GQ; g++) {
            const float* pg = p_s + g * PBLK;
            float spw = red[g*4] + red[g*4+1] + red[g*4+2] + red[g*4+3];
            float ww = wpw_r[g] * __fdividef(1.f, spw + EPSQ);
            wprev_r[g] = ww;
            wprev_s[g * NQ + n] = ww;
            float4* Mrow = (float4*)&M_s[(g * NQ + n) * VQ];
            const float4* ep = (const float4*)(pg + 52);
            const float4* ap = (const float4*)(pg + 72);
            #pragma unroll
            for (int i = 0; i < 5; i++) {
                float4 m = Mrow[i], e = ep[i], a = ap[i];
                m.x = fmaf(ww, a.x, fmaf(-ww * e.x, m.x, m.x));
                m.y = fmaf(ww, a.y, fmaf(-ww * e.y, m.y, m.y));
                m.z = fmaf(ww, a.z, fmaf(-ww * e.z, m.z, m.z));
                m.w = fmaf(ww, a.w, fmaf(-ww * e.w, m.w, m.w));
                Mrow[i] = m;
            }
        }
        // out = sigmoid([h, r] @ Wf + bf)  (warp-per-g, 8 outs x 4 partials of 32)
        {
            int g = warp;
            int o = lane & 7, part = lane >> 3;
            const float4* wv = (const float4*)(WfT_g + o * HTS + part * 32);  // 8 float4
            const float4* cv = (const float4*)(h_t   + g * HTS + part * 32);  // 8 float4
            float acc = 0.f;
            #pragma unroll
            for (int i = 0; i < 8; i++) {
                float4 w = wv[i], c = cv[i];
                acc = fmaf(w.x, c.x, acc); acc = fmaf(w.y, c.y, acc);
                acc = fmaf(w.z, c.z, acc); acc = fmaf(w.w, c.w, acc);
            }
            acc += __shfl_xor_sync(0xffffffffu, acc, 8);
            acc += __shfl_xor_sync(0xffffffffu, acc, 16);
            if (lane < 8)
                out[((b0 + g) * TQ + t) * OQ + o] = fsigmoid_(acc + bfv);
        }
        // prefetch next x_t
        if (t + 1 < TQ && tid < IQ * GQ) {
            int g = tid / IQ, i = tid - g * IQ;
            z_s[i * GQ + g] = x[((b0 + g) * TQ + (t + 1)) * IQ + i];
        }
        __syncthreads();
    }
}

extern "C" void kernel_launch(void* const* d_in, const int* in_sizes, int n_in,
                              void* d_out, int out_size) {
    const float* x      = (const float*)d_in[0];
    const float* Wc     = (const float*)d_in[1];
    const float* bc     = (const float*)d_in[2];
    const float* Wr     = (const float*)d_in[3];
    const float* br     = (const float*)d_in[4];
    const float* Ww     = (const float*)d_in[5];
    const float* bw     = (const float*)d_in[6];
    const float* Wf     = (const float*)d_in[7];
    const float* bf     = (const float*)d_in[8];
    const float* r_bias = (const float*)d_in[9];
    const float* M_bias = (const float*)d_in[10];

    int B = in_sizes[0] / (TQ * IQ);        // 2048
    int grid = B / GQ;                      // 512

    // one-time weight transpose into __device__ scratch (13424 elements)
    prep_kernel<<<53, 256>>>(Wc, Wr, Ww, Wf);

    size_t smem = (size_t)(GQ * NQ * VQ + 4 * GQ * NQ + 32 * GQ + CQ * GQ
                           + GQ * HTS + GQ * PBLK + 48) * sizeof(float);   // 55040 B
    cudaFuncSetAttribute(ntm_kernel, cudaFuncAttributeMaxDynamicSharedMemorySize, (int)smem);

    ntm_kernel<<<grid, BLK, smem>>>(x, bc, br, bw, bf, r_bias, M_bias, (float*)d_out);
}

// round 9
// speedup vs baseline: 1.4387x; 1.4387x over previous
#include <cuda_runtime.h>
#include <math.h>

#define TQ 64
#define IQ 9
#define NQ 128
#define VQ 20
#define CQ 100
#define OQ 8
#define GQ 4
#define BLK 128
#define EPSQ 1e-8f
#define PBLK 96

// p_s per-g block (96 floats, base g*96), vector-aligned:
//  0..19 kr | 20..22 sr, 23 gammar | 24 betar, 25 gr, 26 betaw, 27 gw
//  28..30 sw, 31 gammaw | 32..51 kw | 52..71 e | 72..91 a | 92..95 pad

__device__ __forceinline__ float ftanh_(float x) {
    float xc = fminf(fmaxf(x, -15.f), 15.f);
    float e = __expf(2.f * xc);
    return __fdividef(e - 1.f, e + 1.f);
}
__device__ __forceinline__ float fsoftplus_(float x) {
    return fmaxf(x, 0.f) + __logf(1.f + __expf(-fabsf(x)));
}
__device__ __forceinline__ float fsigmoid_(float x) {
    return __fdividef(1.f, 1.f + __expf(-x));
}
__device__ __forceinline__ float apply_act(int at, float v) {
    switch (at) {
        case 0:  return ftanh_(v);
        case 1:  return fsoftplus_(v);
        case 2:  return fsigmoid_(v);
        case 3:  return __expf(v);
        default: return 1.f + fsoftplus_(v);
    }
}
__device__ __forceinline__ float warp_sum(float v) {
    v += __shfl_xor_sync(0xffffffffu, v, 16);
    v += __shfl_xor_sync(0xffffffffu, v, 8);
    v += __shfl_xor_sync(0xffffffffu, v, 4);
    v += __shfl_xor_sync(0xffffffffu, v, 2);
    v += __shfl_xor_sync(0xffffffffu, v, 1);
    return v;
}

__global__ __launch_bounds__(BLK, 4) void ntm_kernel(
    const float* __restrict__ x,
    const float* __restrict__ Wc, const float* __restrict__ bc,
    const float* __restrict__ Wr, const float* __restrict__ br,
    const float* __restrict__ Ww, const float* __restrict__ bw,
    const float* __restrict__ Wf, const float* __restrict__ bf,
    const float* __restrict__ r_bias, const float* __restrict__ M_bias,
    float* __restrict__ out)
{
    extern __shared__ float sm[];
    float* M_s     = sm;                    // [G][128][20] 10240 (80B rows, 16B aligned)
    float* er_s    = M_s + GQ * NQ * VQ;    // [G][128] content-exp read
    float* ew_s    = er_s + GQ * NQ;        // [G][128] content-exp write
    float* wpr_s   = ew_s + GQ * NQ;        // [G][128] read-head pre-norm sharpened
    float* wprev_s = wpr_s + GQ * NQ;       // [G][128] normalized w_w (prev step)
    float* z_s     = wprev_s + GQ * NQ;     // [32][G]  controller input (x|r|pad)
    float* h_s     = z_s + 32 * GQ;         // [100][G] controller hidden
    float* p_s     = h_s + CQ * GQ;         // [G][96]  head params

    const int tid  = threadIdx.x;
    const int lane = tid & 31;
    const int g    = tid >> 5;              // warp == batch element
    const int b0   = blockIdx.x * GQ;

    // ---- hoisted per-thread constants ----
    float bcv = (tid < CQ) ? bc[tid] : 0.f;
    const float* Wp = Ww; int od = 66, cc = 0, st = 0, at = 0; float bsv = 0.f;
    {
        bool rh = (tid < 26);
        int c = rh ? tid : tid - 26;
        if (rh)            { Wp = Wr; od = 26; cc = c; bsv = br[c]; }
        else if (tid < 92) { cc = c; bsv = bw[c]; }
        if      (c < 20)  { st = (rh ? 0 : 32) + c;       at = 0; }
        else if (c == 20) { st = rh ? 24 : 26;            at = 1; }
        else if (c == 21) { st = rh ? 25 : 27;            at = 2; }
        else if (c < 25)  { st = (rh ? 20 : 28) + (c-22); at = 3; }
        else if (c == 25) { st = rh ? 23 : 31;            at = 4; }
        else if (c < 46)  { st = 52 + (c - 26);           at = 2; }
        else              { st = 72 + (c - 46);           at = 0; }
    }
    float bfv = bf[lane & 7];
    const float* pg = p_s + g * PBLK;

    // ---- init state: this warp owns g's memory; lane owns rows lane+32i ----
    float wprev_r[GQ];                      // own rows' normalized write weights
    {
        const float4* Mb = (const float4*)M_bias;   // [128][5]
        #pragma unroll
        for (int i = 0; i < GQ; i++) {
            int n = lane + 32 * i;
            wprev_r[i] = 0.f;
            wprev_s[g * NQ + n] = 0.f;
            float4* Mr = (float4*)&M_s[(g * NQ + n) * VQ];
            #pragma unroll
            for (int c2 = 0; c2 < 5; c2++) Mr[c2] = Mb[n * 5 + c2];
        }
    }
    if (tid < VQ * GQ) {                    // r0
        int gg = tid & 3, v = tid >> 2;
        z_s[(IQ + v) * GQ + gg] = r_bias[v];
    }
    if (tid < IQ * GQ) {                    // x_0
        int gg = tid / IQ, i = tid - gg * IQ;
        z_s[i * GQ + gg] = x[(b0 + gg) * TQ * IQ + i];
    }
    if (tid < 12) {                         // zero pads: z_s j=29..31
        int j = 29 + (tid >> 2), gg = tid & 3;
        z_s[j * GQ + gg] = 0.f;
    }
    __syncthreads();

    for (int t = 0; t < TQ; t++) {
        // ---- P1: controller h = tanh([x,r] @ Wc + bc)  (coalesced column walk) ----
        if (tid < CQ) {
            float a0 = bcv, a1 = bcv, a2 = bcv, a3 = bcv;
            #pragma unroll
            for (int j = 0; j < IQ + VQ; j++) {
                float w = Wc[j * CQ + tid];
                float4 zv = *(const float4*)&z_s[j * GQ];
                a0 = fmaf(w, zv.x, a0); a1 = fmaf(w, zv.y, a1);
                a2 = fmaf(w, zv.z, a2); a3 = fmaf(w, zv.w, a3);
            }
            *(float4*)&h_s[tid * GQ] =
                make_float4(ftanh_(a0), ftanh_(a1), ftanh_(a2), ftanh_(a3));
        }
        __syncthreads();

        // ---- P2: head matvecs (coalesced) + fused activations ----
        if (tid < 92) {
            float a0 = bsv, a1 = bsv, a2 = bsv, a3 = bsv;
            #pragma unroll 4
            for (int j = 0; j < CQ; j++) {
                float w = Wp[j * od + cc];
                float4 hv = *(const float4*)&h_s[j * GQ];
                a0 = fmaf(w, hv.x, a0); a1 = fmaf(w, hv.y, a1);
                a2 = fmaf(w, hv.z, a2); a3 = fmaf(w, hv.w, a3);
            }
            p_s[0 * PBLK + st] = apply_act(at, a0);
            p_s[1 * PBLK + st] = apply_act(at, a1);
            p_s[2 * PBLK + st] = apply_act(at, a2);
            p_s[3 * PBLK + st] = apply_act(at, a3);
        }
        __syncthreads();

        // ======== warp-local phases: this warp handles batch element g ========
        float4 srv = *(const float4*)(pg + 20);   // sr0,sr1,sr2,gammar
        float4 bv  = *(const float4*)(pg + 24);   // betar, gr, betaw, gw
        float4 swv = *(const float4*)(pg + 28);   // sw0,sw1,sw2,gammaw
        float sr_i = __fdividef(1.f, srv.x + srv.y + srv.z);
        float s_r0 = srv.x * sr_i, s_r1 = srv.y * sr_i, s_r2 = srv.z * sr_i;
        float sw_i = __fdividef(1.f, swv.x + swv.y + swv.z);
        float s_w0 = swv.x * sw_i, s_w1 = swv.y * sw_i, s_w2 = swv.z * sw_i;

        // ---- C1: content addressing, 4 rows, both heads ----
        float dr[4] = {0,0,0,0}, dw[4] = {0,0,0,0}, n2[4] = {0,0,0,0};
        float kr2 = 0.f, kw2 = 0.f;
        #pragma unroll
        for (int c = 0; c < 5; c++) {
            float4 krc = ((const float4*)pg)[c];
            float4 kwc = ((const float4*)(pg + 32))[c];
            kr2 = fmaf(krc.x,krc.x, fmaf(krc.y,krc.y, fmaf(krc.z,krc.z, fmaf(krc.w,krc.w, kr2))));
            kw2 = fmaf(kwc.x,kwc.x, fmaf(kwc.y,kwc.y, fmaf(kwc.z,kwc.z, fmaf(kwc.w,kwc.w, kw2))));
            #pragma unroll
            for (int i = 0; i < 4; i++) {
                float4 m = *(const float4*)&M_s[(g * NQ + lane + 32 * i) * VQ + c * 4];
                dr[i] = fmaf(krc.x,m.x, fmaf(krc.y,m.y, fmaf(krc.z,m.z, fmaf(krc.w,m.w, dr[i]))));
                dw[i] = fmaf(kwc.x,m.x, fmaf(kwc.y,m.y, fmaf(kwc.z,m.z, fmaf(kwc.w,m.w, dw[i]))));
                n2[i] = fmaf(m.x,m.x, fmaf(m.y,m.y, fmaf(m.z,m.z, fmaf(m.w,m.w, n2[i]))));
            }
        }
        float knr = sqrtf(kr2), knw = sqrtf(kw2);
        float er_r[4], ew_r[4], ser = 0.f, sew = 0.f;
        #pragma unroll
        for (int i = 0; i < 4; i++) {
            float mn = sqrtf(n2[i]);
            er_r[i] = __expf(bv.x * __fdividef(dr[i], knr * mn + EPSQ));
            ew_r[i] = __expf(bv.z * __fdividef(dw[i], knw * mn + EPSQ));
            er_s[g * NQ + lane + 32 * i] = er_r[i];
            ew_s[g * NQ + lane + 32 * i] = ew_r[i];
            ser += er_r[i]; sew += ew_r[i];
        }
        ser = warp_sum(ser); sew = warp_sum(sew);
        __syncwarp();

        // ---- C2: read-head interpolation + circular conv + sharpen ----
        float ginv = bv.y * __fdividef(1.f, ser);
        float omg  = 1.f - bv.y;
        float wpr_r[4], ssp = 0.f;
        #pragma unroll
        for (int i = 0; i < 4; i++) {
            int n = lane + 32 * i, nm = (n - 1) & 127, np = (n + 1) & 127;
            float wg_m = ginv * er_s[g * NQ + nm] + omg * wprev_s[g * NQ + nm];
            float wg_0 = ginv * er_r[i]           + omg * wprev_r[i];
            float wg_p = ginv * er_s[g * NQ + np] + omg * wprev_s[g * NQ + np];
            float ws = s_r0 * wg_p + s_r1 * wg_0 + s_r2 * wg_m;
            float wpr = __expf(srv.w * __logf(ws));
            wpr_s[g * NQ + n] = wpr;
            wpr_r[i] = wpr; ssp += wpr;
        }
        float sp = warp_sum(ssp);
        float invsp = __fdividef(1.f, sp + EPSQ);
        __syncwarp();

        // ---- C3: write-head interpolation + conv + sharpen (w_prev = w_r) ----
        float gwinv = bv.w * __fdividef(1.f, sew);
        float omgsp = (1.f - bv.w) * invsp;
        float wpw_r[4], swp = 0.f;
        #pragma unroll
        for (int i = 0; i < 4; i++) {
            int n = lane + 32 * i, nm = (n - 1) & 127, np = (n + 1) & 127;
            float w_m = gwinv * ew_s[g * NQ + nm] + omgsp * wpr_s[g * NQ + nm];
            float w_0 = gwinv * ew_r[i]           + omgsp * wpr_r[i];
            float w_p = gwinv * ew_s[g * NQ + np] + omgsp * wpr_s[g * NQ + np];
            float ws = s_w0 * w_p + s_w1 * w_0 + s_w2 * w_m;
            float wpw = __expf(swv.w * __logf(ws));
            wpw_r[i] = wpw; swp += wpw;
        }
        float spw = warp_sum(swp);
        float invspw = __fdividef(1.f, spw + EPSQ);
        #pragma unroll
        for (int i = 0; i < 4; i++) {
            float ww = wpw_r[i] * invspw;
            wprev_r[i] = ww;
            wprev_s[g * NQ + lane + 32 * i] = ww;   // neighbors need it NEXT step
        }

        // ---- C4: fused r-readout (old M, w_r) + M update (w_w); M is lane-private ----
        float wr0 = wpr_r[0] * invsp, wr1 = wpr_r[1] * invsp,
              wr2 = wpr_r[2] * invsp, wr3 = wpr_r[3] * invsp;
        float racc[VQ];
        #pragma unroll
        for (int c = 0; c < 5; c++) {
            float4 e4 = ((const float4*)(pg + 52))[c];
            float4 a4 = ((const float4*)(pg + 72))[c];
            float rx = 0.f, ry = 0.f, rz = 0.f, rw = 0.f;
            #pragma unroll
            for (int i = 0; i < 4; i++) {
                float wri = (i == 0) ? wr0 : (i == 1) ? wr1 : (i == 2) ? wr2 : wr3;
                float wwi = wprev_r[i];
                float4* mp = (float4*)&M_s[(g * NQ + lane + 32 * i) * VQ + c * 4];
                float4 m = *mp;
                rx = fmaf(wri, m.x, rx); ry = fmaf(wri, m.y, ry);
                rz = fmaf(wri, m.z, rz); rw = fmaf(wri, m.w, rw);
                m.x = fmaf(wwi, a4.x, fmaf(-wwi * e4.x, m.x, m.x));
                m.y = fmaf(wwi, a4.y, fmaf(-wwi * e4.y, m.y, m.y));
                m.z = fmaf(wwi, a4.z, fmaf(-wwi * e4.z, m.z, m.z));
                m.w = fmaf(wwi, a4.w, fmaf(-wwi * e4.w, m.w, m.w));
                *mp = m;
            }
            racc[c*4+0] = rx; racc[c*4+1] = ry; racc[c*4+2] = rz; racc[c*4+3] = rw;
        }
        #pragma unroll
        for (int v = 0; v < VQ; v++) racc[v] = warp_sum(racc[v]);
        if (lane == 0) {
            #pragma unroll
            for (int v = 0; v < VQ; v++) z_s[(IQ + v) * GQ + g] = racc[v];
        }
        __syncwarp();

        // ---- out = sigmoid([h, r] @ Wf + bf)  (8 outs x 4 partials of 30) ----
        {
            int o = lane & 7, part = lane >> 3;
            float acc = 0.f;
            int j0 = part * 30;
            #pragma unroll 5
            for (int j = j0; j < j0 + 30; j++) {
                float c = (j < CQ) ? h_s[j * GQ + g] : z_s[(IQ + (j - CQ)) * GQ + g];
                acc = fmaf(c, Wf[j * OQ + o], acc);
            }
            acc += __shfl_xor_sync(0xffffffffu, acc, 8);
            acc += __shfl_xor_sync(0xffffffffu, acc, 16);
            if (lane < 8)
                out[((b0 + g) * TQ + t) * OQ + o] = fsigmoid_(acc + bfv);
        }
        // prefetch next x_t (x-part of z_s untouched by warp phases)
        if (t + 1 < TQ && tid < IQ * GQ) {
            int gg = tid / IQ, i = tid - gg * IQ;
            z_s[i * GQ + gg] = x[((b0 + gg) * TQ + (t + 1)) * IQ + i];
        }
        __syncthreads();
    }
}

extern "C" void kernel_launch(void* const* d_in, const int* in_sizes, int n_in,
                              void* d_out, int out_size) {
    const float* x      = (const float*)d_in[0];
    const float* Wc     = (const float*)d_in[1];
    const float* bc     = (const float*)d_in[2];
    const float* Wr     = (const float*)d_in[3];
    const float* br     = (const float*)d_in[4];
    const float* Ww     = (const float*)d_in[5];
    const float* bw     = (const float*)d_in[6];
    const float* Wf     = (const float*)d_in[7];
    const float* bf     = (const float*)d_in[8];
    const float* r_bias = (const float*)d_in[9];
    const float* M_bias = (const float*)d_in[10];

    int B = in_sizes[0] / (TQ * IQ);        // 2048
    int grid = B / GQ;                      // 512

    size_t smem = (size_t)(GQ * NQ * VQ + 4 * GQ * NQ + 32 * GQ + CQ * GQ
                           + GQ * PBLK) * sizeof(float);   // 52800 B
    cudaFuncSetAttribute(ntm_kernel, cudaFuncAttributeMaxDynamicSharedMemorySize, (int)smem);

    ntm_kernel<<<grid, BLK, smem>>>(x, Wc, bc, Wr, br, Ww, bw, Wf, bf,
                                    r_bias, M_bias, (float*)d_out);
}

// round 10
// speedup vs baseline: 1.8264x; 1.2695x over previous
#include <cuda_runtime.h>
#include <math.h>

#define TQ 64
#define IQ 9
#define NQ 128
#define VQ 20
#define CQ 100
#define OQ 8
#define GQ 4
#define BLK 128
#define EPSQ 1e-8f
#define PBLK 96

// p_s per-g block (96 floats), vector-aligned:
//  0..19 kr | 20..22 sr, 23 gammar | 24 betar, 25 gr, 26 betaw, 27 gw
//  28..30 sw, 31 gammaw | 32..51 kw | 52..71 e | 72..91 a | 92..95 pad

// 4-j interleaved weights: W4[jb][col][q] = W[(4jb+q)*od + col]
__device__ __align__(16) float Wc4_g[8 * CQ * 4];    // 3200 (j padded 29->32)
__device__ __align__(16) float Wr4_g[25 * 26 * 4];   // 2600
__device__ __align__(16) float Ww4_g[25 * 66 * 4];   // 6600

__global__ void prep_kernel(const float* __restrict__ Wc, const float* __restrict__ Wr,
                            const float* __restrict__ Ww) {
    int i = blockIdx.x * blockDim.x + threadIdx.x;
    if (i < 3200) {
        int jb = i / 400, rem = i % 400, c = rem >> 2, q = rem & 3, j = jb * 4 + q;
        Wc4_g[i] = (j < 29) ? Wc[j * CQ + c] : 0.f;
    }
    int j2 = i - 3200;
    if (j2 >= 0 && j2 < 2600) {
        int jb = j2 / 104, rem = j2 % 104, c = rem >> 2, q = rem & 3;
        Wr4_g[j2] = Wr[(jb * 4 + q) * 26 + c];
    }
    int k2 = i - 5800;
    if (k2 >= 0 && k2 < 6600) {
        int jb = k2 / 264, rem = k2 % 264, c = rem >> 2, q = rem & 3;
        Ww4_g[k2] = Ww[(jb * 4 + q) * 66 + c];
    }
}

__device__ __forceinline__ float ftanh_(float x) {
    float xc = fminf(fmaxf(x, -15.f), 15.f);
    float e = __expf(2.f * xc);
    return __fdividef(e - 1.f, e + 1.f);
}
__device__ __forceinline__ float fsoftplus_(float x) {
    return fmaxf(x, 0.f) + __logf(1.f + __expf(-fabsf(x)));
}
__device__ __forceinline__ float fsigmoid_(float x) {
    return __fdividef(1.f, 1.f + __expf(-x));
}
__device__ __forceinline__ float apply_act(int at, float v) {
    switch (at) {
        case 0:  return ftanh_(v);
        case 1:  return fsoftplus_(v);
        case 2:  return fsigmoid_(v);
        case 3:  return __expf(v);
        default: return 1.f + fsoftplus_(v);
    }
}
__device__ __forceinline__ float warp_sum(float v) {
    v += __shfl_xor_sync(0xffffffffu, v, 16);
    v += __shfl_xor_sync(0xffffffffu, v, 8);
    v += __shfl_xor_sync(0xffffffffu, v, 4);
    v += __shfl_xor_sync(0xffffffffu, v, 2);
    v += __shfl_xor_sync(0xffffffffu, v, 1);
    return v;
}

__global__ __launch_bounds__(BLK, 4) void ntm_kernel(
    const float* __restrict__ x,
    const float* __restrict__ bc, const float* __restrict__ br,
    const float* __restrict__ bw, const float* __restrict__ bf,
    const float* __restrict__ Wf,
    const float* __restrict__ r_bias, const float* __restrict__ M_bias,
    float* __restrict__ out)
{
    extern __shared__ float sm[];
    float* M_s = sm;                        // [G][128][20] 10240 (80B rows)
    float* z_s = M_s + GQ * NQ * VQ;        // [32][G]  controller input (x|r|pad)
    float* h_s = z_s + 32 * GQ;             // [100][G] controller hidden
    float* p_s = h_s + CQ * GQ;             // [G][96]  head params

    const int tid  = threadIdx.x;
    const int lane = tid & 31;
    const int g    = tid >> 5;              // warp == batch element
    const int b0   = blockIdx.x * GQ;

    // ---- hoisted per-thread constants ----
    float bcv = (tid < CQ) ? bc[tid] : 0.f;
    const float4* Wp4 = (const float4*)Ww4_g;
    int od = 66, st = 0, at = 0; float bsv = 0.f;
    {
        bool rh = (tid < 26);
        int c = rh ? tid : tid - 26;
        if (rh)            { Wp4 = (const float4*)Wr4_g + c; od = 26; bsv = br[c]; }
        else if (tid < 92) { Wp4 = (const float4*)Ww4_g + c; bsv = bw[c]; }
        if      (c < 20)  { st = (rh ? 0 : 32) + c;       at = 0; }
        else if (c == 20) { st = rh ? 24 : 26;            at = 1; }
        else if (c == 21) { st = rh ? 25 : 27;            at = 2; }
        else if (c < 25)  { st = (rh ? 20 : 28) + (c-22); at = 3; }
        else if (c == 25) { st = rh ? 23 : 31;            at = 4; }
        else if (c < 46)  { st = 52 + (c - 26);           at = 2; }
        else              { st = 72 + (c - 46);           at = 0; }
    }
    float bfv = bf[lane & 7];
    const float* pg = p_s + g * PBLK;

    // ---- init state: lane owns rows lane+32i of batch g ----
    float wprev_r[GQ];
    {
        const float4* Mb = (const float4*)M_bias;   // [128][5]
        #pragma unroll
        for (int i = 0; i < GQ; i++) {
            int n = lane + 32 * i;
            wprev_r[i] = 0.f;
            float4* Mr = (float4*)&M_s[(g * NQ + n) * VQ];
            #pragma unroll
            for (int c2 = 0; c2 < 5; c2++) Mr[c2] = Mb[n * 5 + c2];
        }
    }
    if (tid < VQ * GQ) {                    // r0
        int gg = tid & 3, v = tid >> 2;
        z_s[(IQ + v) * GQ + gg] = r_bias[v];
    }
    if (tid < IQ * GQ) {                    // x_0
        int gg = tid / IQ, i = tid - gg * IQ;
        z_s[i * GQ + gg] = x[(b0 + gg) * TQ * IQ + i];
    }
    if (tid < 12) {                         // zero pads: z_s j=29..31
        int j = 29 + (tid >> 2), gg = tid & 3;
        z_s[j * GQ + gg] = 0.f;
    }
    __syncthreads();

    for (int t = 0; t < TQ; t++) {
        // ---- P1: controller h = tanh([x,r] @ Wc + bc)  (LDG.128 weights) ----
        if (tid < CQ) {
            const float4* wp = (const float4*)Wc4_g + tid;   // + jb*CQ
            const float4* z4 = (const float4*)z_s;
            float a0 = bcv, a1 = bcv, a2 = bcv, a3 = bcv;
            #pragma unroll
            for (int jb = 0; jb < 8; jb++) {
                float4 w  = wp[jb * CQ];
                float4 za = z4[4*jb+0], zb = z4[4*jb+1], zc = z4[4*jb+2], zd = z4[4*jb+3];
                a0 = fmaf(w.x, za.x, a0); a1 = fmaf(w.x, za.y, a1);
                a2 = fmaf(w.x, za.z, a2); a3 = fmaf(w.x, za.w, a3);
                a0 = fmaf(w.y, zb.x, a0); a1 = fmaf(w.y, zb.y, a1);
                a2 = fmaf(w.y, zb.z, a2); a3 = fmaf(w.y, zb.w, a3);
                a0 = fmaf(w.z, zc.x, a0); a1 = fmaf(w.z, zc.y, a1);
                a2 = fmaf(w.z, zc.z, a2); a3 = fmaf(w.z, zc.w, a3);
                a0 = fmaf(w.w, zd.x, a0); a1 = fmaf(w.w, zd.y, a1);
                a2 = fmaf(w.w, zd.z, a2); a3 = fmaf(w.w, zd.w, a3);
            }
            *(float4*)&h_s[tid * GQ] =
                make_float4(ftanh_(a0), ftanh_(a1), ftanh_(a2), ftanh_(a3));
        }
        __syncthreads();

        // ---- P2: head matvecs (LDG.128 weights) + fused activations ----
        if (tid < 92) {
            const float4* h4 = (const float4*)h_s;
            float a0 = bsv, a1 = bsv, a2 = bsv, a3 = bsv;
            #pragma unroll 5
            for (int jb = 0; jb < 25; jb++) {
                float4 w  = Wp4[jb * od];
                float4 ha = h4[4*jb+0], hb = h4[4*jb+1], hc = h4[4*jb+2], hd = h4[4*jb+3];
                a0 = fmaf(w.x, ha.x, a0); a1 = fmaf(w.x, ha.y, a1);
                a2 = fmaf(w.x, ha.z, a2); a3 = fmaf(w.x, ha.w, a3);
                a0 = fmaf(w.y, hb.x, a0); a1 = fmaf(w.y, hb.y, a1);
                a2 = fmaf(w.y, hb.z, a2); a3 = fmaf(w.y, hb.w, a3);
                a0 = fmaf(w.z, hc.x, a0); a1 = fmaf(w.z, hc.y, a1);
                a2 = fmaf(w.z, hc.z, a2); a3 = fmaf(w.z, hc.w, a3);
                a0 = fmaf(w.w, hd.x, a0); a1 = fmaf(w.w, hd.y, a1);
                a2 = fmaf(w.w, hd.z, a2); a3 = fmaf(w.w, hd.w, a3);
            }
            p_s[0 * PBLK + st] = apply_act(at, a0);
            p_s[1 * PBLK + st] = apply_act(at, a1);
            p_s[2 * PBLK + st] = apply_act(at, a2);
            p_s[3 * PBLK + st] = apply_act(at, a3);
        }
        __syncthreads();

        // ======== warp-local phases (batch g); neighbors via shfl ========
        float4 srv = *(const float4*)(pg + 20);
        float4 bv  = *(const float4*)(pg + 24);
        float4 swv = *(const float4*)(pg + 28);
        float sr_i = __fdividef(1.f, srv.x + srv.y + srv.z);
        float s_r0 = srv.x * sr_i, s_r1 = srv.y * sr_i, s_r2 = srv.z * sr_i;
        float sw_i = __fdividef(1.f, swv.x + swv.y + swv.z);
        float s_w0 = swv.x * sw_i, s_w1 = swv.y * sw_i, s_w2 = swv.z * sw_i;

        // ---- C1: content addressing, 4 rows, both heads ----
        float dr[4] = {0,0,0,0}, dw[4] = {0,0,0,0}, n2[4] = {0,0,0,0};
        float kr2 = 0.f, kw2 = 0.f;
        #pragma unroll
        for (int c = 0; c < 5; c++) {
            float4 krc = ((const float4*)pg)[c];
            float4 kwc = ((const float4*)(pg + 32))[c];
            kr2 = fmaf(krc.x,krc.x, fmaf(krc.y,krc.y, fmaf(krc.z,krc.z, fmaf(krc.w,krc.w, kr2))));
            kw2 = fmaf(kwc.x,kwc.x, fmaf(kwc.y,kwc.y, fmaf(kwc.z,kwc.z, fmaf(kwc.w,kwc.w, kw2))));
            #pragma unroll
            for (int i = 0; i < 4; i++) {
                float4 m = *(const float4*)&M_s[(g * NQ + lane + 32 * i) * VQ + c * 4];
                dr[i] = fmaf(krc.x,m.x, fmaf(krc.y,m.y, fmaf(krc.z,m.z, fmaf(krc.w,m.w, dr[i]))));
                dw[i] = fmaf(kwc.x,m.x, fmaf(kwc.y,m.y, fmaf(kwc.z,m.z, fmaf(kwc.w,m.w, dw[i]))));
                n2[i] = fmaf(m.x,m.x, fmaf(m.y,m.y, fmaf(m.z,m.z, fmaf(m.w,m.w, n2[i]))));
            }
        }
        float knr = sqrtf(kr2), knw = sqrtf(kw2);
        float er_r[4], ew_r[4], ser = 0.f, sew = 0.f;
        #pragma unroll
        for (int i = 0; i < 4; i++) {
            float mn = sqrtf(n2[i]);
            er_r[i] = __expf(bv.x * __fdividef(dr[i], knr * mn + EPSQ));
            ew_r[i] = __expf(bv.z * __fdividef(dw[i], knw * mn + EPSQ));
            ser += er_r[i]; sew += ew_r[i];
        }
        ser = warp_sum(ser); sew = warp_sum(sew);

        // ---- C2: read-head interp (regs) + conv via shfl + sharpen ----
        float ginv = bv.y * __fdividef(1.f, ser);
        float omg  = 1.f - bv.y;
        float wg_r[4];
        #pragma unroll
        for (int i = 0; i < 4; i++)
            wg_r[i] = fmaf(ginv, er_r[i], omg * wprev_r[i]);
        float wpr_r[4], ssp = 0.f;
        #pragma unroll
        for (int i = 0; i < 4; i++) {
            float tnp = (lane == 0)  ? wg_r[(i + 1) & 3] : wg_r[i];
            float tnm = (lane == 31) ? wg_r[(i + 3) & 3] : wg_r[i];
            float w_p = __shfl_sync(0xffffffffu, tnp, (lane + 1)  & 31);
            float w_m = __shfl_sync(0xffffffffu, tnm, (lane + 31) & 31);
            float ws  = s_r0 * w_p + s_r1 * wg_r[i] + s_r2 * w_m;
            wpr_r[i]  = __expf(srv.w * __logf(ws));
            ssp += wpr_r[i];
        }
        float sp = warp_sum(ssp);
        float invsp = __fdividef(1.f, sp + EPSQ);

        // ---- C3: write-head interp + conv via shfl + sharpen ----
        float gwinv = bv.w * __fdividef(1.f, sew);
        float omgsp = (1.f - bv.w) * invsp;
        float wt_r[4];
        #pragma unroll
        for (int i = 0; i < 4; i++)
            wt_r[i] = fmaf(gwinv, ew_r[i], omgsp * wpr_r[i]);
        float wpw_r[4], swp = 0.f;
        #pragma unroll
        for (int i = 0; i < 4; i++) {
            float tnp = (lane == 0)  ? wt_r[(i + 1) & 3] : wt_r[i];
            float tnm = (lane == 31) ? wt_r[(i + 3) & 3] : wt_r[i];
            float w_p = __shfl_sync(0xffffffffu, tnp, (lane + 1)  & 31);
            float w_m = __shfl_sync(0xffffffffu, tnm, (lane + 31) & 31);
            float ws  = s_w0 * w_p + s_w1 * wt_r[i] + s_w2 * w_m;
            wpw_r[i]  = __expf(swv.w * __logf(ws));
            swp += wpw_r[i];
        }
        float spw = warp_sum(swp);
        float invspw = __fdividef(1.f, spw + EPSQ);
        #pragma unroll
        for (int i = 0; i < 4; i++)
            wprev_r[i] = wpw_r[i] * invspw;          // carried in regs to next step

        // ---- C4: fused r-readout (old M, w_r) + M update (w_w) ----
        float wr0 = wpr_r[0] * invsp, wr1 = wpr_r[1] * invsp,
              wr2 = wpr_r[2] * invsp, wr3 = wpr_r[3] * invsp;
        float racc[VQ];
        #pragma unroll
        for (int c = 0; c < 5; c++) {
            float4 e4 = ((const float4*)(pg + 52))[c];
            float4 a4 = ((const float4*)(pg + 72))[c];
            float rx = 0.f, ry = 0.f, rz = 0.f, rw = 0.f;
            #pragma unroll
            for (int i = 0; i < 4; i++) {
                float wri = (i == 0) ? wr0 : (i == 1) ? wr1 : (i == 2) ? wr2 : wr3;
                float wwi = wprev_r[i];
                float4* mp = (float4*)&M_s[(g * NQ + lane + 32 * i) * VQ + c * 4];
                float4 m = *mp;
                rx = fmaf(wri, m.x, rx); ry = fmaf(wri, m.y, ry);
                rz = fmaf(wri, m.z, rz); rw = fmaf(wri, m.w, rw);
                m.x = fmaf(wwi, a4.x, fmaf(-wwi * e4.x, m.x, m.x));
                m.y = fmaf(wwi, a4.y, fmaf(-wwi * e4.y, m.y, m.y));
                m.z = fmaf(wwi, a4.z, fmaf(-wwi * e4.z, m.z, m.z));
                m.w = fmaf(wwi, a4.w, fmaf(-wwi * e4.w, m.w, m.w));
                *mp = m;
            }
            racc[c*4+0] = rx; racc[c*4+1] = ry; racc[c*4+2] = rz; racc[c*4+3] = rw;
        }
        #pragma unroll
        for (int v = 0; v < VQ; v++) racc[v] = warp_sum(racc[v]);
        if (lane == 0) {
            #pragma unroll
            for (int v = 0; v < VQ; v++) z_s[(IQ + v) * GQ + g] = racc[v];
        }
        __syncwarp();

        // ---- out = sigmoid([h, r] @ Wf + bf)  (8 outs x 4 partials of 30) ----
        {
            int o = lane & 7, part = lane >> 3;
            float acc = 0.f;
            int j0 = part * 30;
            #pragma unroll 5
            for (int j = j0; j < j0 + 30; j++) {
                float c = (j < CQ) ? h_s[j * GQ + g] : z_s[(IQ + (j - CQ)) * GQ + g];
                acc = fmaf(c, Wf[j * OQ + o], acc);
            }
            acc += __shfl_xor_sync(0xffffffffu, acc, 8);
            acc += __shfl_xor_sync(0xffffffffu, acc, 16);
            if (lane < 8)
                out[((b0 + g) * TQ + t) * OQ + o] = fsigmoid_(acc + bfv);
        }
        // prefetch next x_t
        if (t + 1 < TQ && tid < IQ * GQ) {
            int gg = tid / IQ, i = tid - gg * IQ;
            z_s[i * GQ + gg] = x[((b0 + gg) * TQ + (t + 1)) * IQ + i];
        }
        __syncthreads();
    }
}

extern "C" void kernel_launch(void* const* d_in, const int* in_sizes, int n_in,
                              void* d_out, int out_size) {
    const float* x      = (const float*)d_in[0];
    const float* Wc     = (const float*)d_in[1];
    const float* bc     = (const float*)d_in[2];
    const float* Wr     = (const float*)d_in[3];
    const float* br     = (const float*)d_in[4];
    const float* Ww     = (const float*)d_in[5];
    const float* bw     = (const float*)d_in[6];
    const float* Wf     = (const float*)d_in[7];
    const float* bf     = (const float*)d_in[8];
    const float* r_bias = (const float*)d_in[9];
    const float* M_bias = (const float*)d_in[10];

    int B = in_sizes[0] / (TQ * IQ);        // 2048
    int grid = B / GQ;                      // 512

    prep_kernel<<<49, 256>>>(Wc, Wr, Ww);   // 12400 elements

    size_t smem = (size_t)(GQ * NQ * VQ + 32 * GQ + CQ * GQ + GQ * PBLK)
                  * sizeof(float);          // 44608 B
    cudaFuncSetAttribute(ntm_kernel, cudaFuncAttributeMaxDynamicSharedMemorySize, (int)smem);

    ntm_kernel<<<grid, BLK, smem>>>(x, bc, br, bw, bf, Wf, r_bias, M_bias, (float*)d_out);
}

// round 11
// speedup vs baseline: 2.0775x; 1.1375x over previous
#include <cuda_runtime.h>
#include <math.h>

#define TQ 64
#define IQ 9
#define NQ 128
#define VQ 20
#define CQ 100
#define OQ 8
#define GQ 4
#define BLK 128
#define EPSQ 1e-8f
#define PBLK 96
#define HTS 128   // h_t row: h(100) | r(20) | zero pad(8)

// p_s per-g block (96 floats), vector-aligned:
//  0..19 kr | 20..22 sr, 23 gammar | 24 betar, 25 gr, 26 betaw, 27 gw
//  28..30 sw, 31 gammaw | 32..51 kw | 52..71 e | 72..91 a | 92..95 pad

// 4-j interleaved weights: W4[jb][col][q] = W[(4jb+q)*od + col]
__device__ __align__(16) float Wc4_g[8 * CQ * 4];    // 3200 (j padded 29->32)
__device__ __align__(16) float Wr4_g[25 * 26 * 4];   // 2600
__device__ __align__(16) float Ww4_g[25 * 66 * 4];   // 6600
__device__ __align__(16) float Wf4_g[32 * OQ * 4];   // 4096 (j padded 120->128)

__global__ void prep_kernel(const float* __restrict__ Wc, const float* __restrict__ Wr,
                            const float* __restrict__ Ww, const float* __restrict__ Wf) {
    int i = blockIdx.x * blockDim.x + threadIdx.x;
    if (i < 3200) {
        int jb = i / 400, rem = i % 400, c = rem >> 2, q = rem & 3, j = jb * 4 + q;
        Wc4_g[i] = (j < 29) ? Wc[j * CQ + c] : 0.f;
    }
    int j2 = i - 3200;
    if (j2 >= 0 && j2 < 2600) {
        int jb = j2 / 104, rem = j2 % 104, c = rem >> 2, q = rem & 3;
        Wr4_g[j2] = Wr[(jb * 4 + q) * 26 + c];
    }
    int k2 = i - 5800;
    if (k2 >= 0 && k2 < 6600) {
        int jb = k2 / 264, rem = k2 % 264, c = rem >> 2, q = rem & 3;
        Ww4_g[k2] = Ww[(jb * 4 + q) * 66 + c];
    }
    int l2 = i - 12400;
    if (l2 >= 0 && l2 < 4096) {
        int jb = l2 / 32, rem = l2 % 32, o = rem >> 2, q = rem & 3, j = jb * 4 + q;
        Wf4_g[l2] = (j < 120) ? Wf[j * OQ + o] : 0.f;
    }
}

typedef unsigned long long ull;
__device__ __forceinline__ ull pk2(float v) {
    ull r; asm("mov.b64 %0, {%1, %1};" : "=l"(r) : "f"(v)); return r;
}
__device__ __forceinline__ float2 upk2(ull v) {
    float2 r; asm("mov.b64 {%0, %1}, %2;" : "=f"(r.x), "=f"(r.y) : "l"(v)); return r;
}
__device__ __forceinline__ ull ffma2(ull a, ull b, ull c) {
    ull d; asm("fma.rn.f32x2 %0, %1, %2, %3;" : "=l"(d) : "l"(a), "l"(b), "l"(c)); return d;
}
__device__ __forceinline__ ull fmul2(ull a, ull b) {
    ull d; asm("mul.rn.f32x2 %0, %1, %2;" : "=l"(d) : "l"(a), "l"(b)); return d;
}
__device__ __forceinline__ ull d2l(double v) { return __double_as_longlong(v); }
__device__ __forceinline__ double l2d(ull v) { return __longlong_as_double(v); }

__device__ __forceinline__ float ftanh_(float x) {
    float xc = fminf(fmaxf(x, -15.f), 15.f);
    float e = __expf(2.f * xc);
    return __fdividef(e - 1.f, e + 1.f);
}
__device__ __forceinline__ float fsoftplus_(float x) {
    return fmaxf(x, 0.f) + __logf(1.f + __expf(-fabsf(x)));
}
__device__ __forceinline__ float fsigmoid_(float x) {
    return __fdividef(1.f, 1.f + __expf(-x));
}
__device__ __forceinline__ float apply_act(int at, float v) {
    switch (at) {
        case 0:  return ftanh_(v);
        case 1:  return fsoftplus_(v);
        case 2:  return fsigmoid_(v);
        case 3:  return __expf(v);
        default: return 1.f + fsoftplus_(v);
    }
}
__device__ __forceinline__ float warp_sum(float v) {
    v += __shfl_xor_sync(0xffffffffu, v, 16);
    v += __shfl_xor_sync(0xffffffffu, v, 8);
    v += __shfl_xor_sync(0xffffffffu, v, 4);
    v += __shfl_xor_sync(0xffffffffu, v, 2);
    v += __shfl_xor_sync(0xffffffffu, v, 1);
    return v;
}
__device__ __forceinline__ ull warp_sum2(ull v) {
    #pragma unroll
    for (int k = 16; k; k >>= 1) {
        ull o = __shfl_xor_sync(0xffffffffu, v, k);
        asm("add.rn.f32x2 %0, %0, %1;" : "+l"(v) : "l"(o));
    }
    return v;
}

__global__ __launch_bounds__(BLK, 4) void ntm_kernel(
    const float* __restrict__ x,
    const float* __restrict__ bc, const float* __restrict__ br,
    const float* __restrict__ bw, const float* __restrict__ bf,
    const float* __restrict__ r_bias, const float* __restrict__ M_bias,
    float* __restrict__ out)
{
    extern __shared__ float sm[];
    float* M_s = sm;                        // [G][128][20] 10240 (80B rows)
    float* z_s = M_s + GQ * NQ * VQ;        // [32][G]  controller input (x|r|pad)
    float* h_s = z_s + 32 * GQ;             // [100][G] controller hidden
    float* p_s = h_s + CQ * GQ;             // [G][96]  head params
    float* h_t = p_s + GQ * PBLK;           // [G][128] [h|r|pad] per-g contiguous

    const int tid  = threadIdx.x;
    const int lane = tid & 31;
    const int g    = tid >> 5;              // warp == batch element
    const int b0   = blockIdx.x * GQ;

    // ---- hoisted per-thread constants ----
    float bcv = (tid < CQ) ? bc[tid] : 0.f;
    const float4* Wp4 = (const float4*)Ww4_g;
    int od = 66, st = 0, at = 0; float bsv = 0.f;
    {
        bool rh = (tid < 26);
        int c = rh ? tid : tid - 26;
        if (rh)            { Wp4 = (const float4*)Wr4_g + c; od = 26; bsv = br[c]; }
        else if (tid < 92) { Wp4 = (const float4*)Ww4_g + c; bsv = bw[c]; }
        if      (c < 20)  { st = (rh ? 0 : 32) + c;       at = 0; }
        else if (c == 20) { st = rh ? 24 : 26;            at = 1; }
        else if (c == 21) { st = rh ? 25 : 27;            at = 2; }
        else if (c < 25)  { st = (rh ? 20 : 28) + (c-22); at = 3; }
        else if (c == 25) { st = rh ? 23 : 31;            at = 4; }
        else if (c < 46)  { st = 52 + (c - 26);           at = 2; }
        else              { st = 72 + (c - 46);           at = 0; }
    }
    float bfv = bf[lane & 7];
    const float* pg = p_s + g * PBLK;

    // ---- init state ----
    float wprev_r[GQ];
    {
        const float4* Mb = (const float4*)M_bias;
        #pragma unroll
        for (int i = 0; i < GQ; i++) {
            int n = lane + 32 * i;
            wprev_r[i] = 0.f;
            float4* Mr = (float4*)&M_s[(g * NQ + n) * VQ];
            #pragma unroll
            for (int c2 = 0; c2 < 5; c2++) Mr[c2] = Mb[n * 5 + c2];
        }
    }
    if (tid < VQ * GQ) {                    // r0 into z_s and h_t
        int gg = tid & 3, v = tid >> 2;
        z_s[(IQ + v) * GQ + gg] = r_bias[v];
        h_t[gg * HTS + 100 + v] = r_bias[v];
    }
    if (tid < IQ * GQ) {                    // x_0
        int gg = tid / IQ, i = tid - gg * IQ;
        z_s[i * GQ + gg] = x[(b0 + gg) * TQ * IQ + i];
    }
    if (tid < 12) {                         // zero pads: z_s j=29..31
        int j = 29 + (tid >> 2), gg = tid & 3;
        z_s[j * GQ + gg] = 0.f;
    }
    if (tid < 32) {                         // zero pads: h_t[g][120..127]
        int gg = tid >> 3;
        h_t[gg * HTS + 120 + (tid & 7)] = 0.f;
    }
    __syncthreads();

    for (int t = 0; t < TQ; t++) {
        // ---- P1: controller h = tanh([x,r] @ Wc + bc)  (packed f32x2) ----
        if (tid < CQ) {
            const float4*  wp = (const float4*)Wc4_g + tid;
            const double2* z2 = (const double2*)z_s;
            ull a01 = pk2(bcv), a23 = a01;
            #pragma unroll
            for (int jb = 0; jb < 8; jb++) {
                float4 w = wp[jb * CQ];
                double2 za = z2[4*jb+0], zb = z2[4*jb+1], zc = z2[4*jb+2], zd = z2[4*jb+3];
                ull wx = pk2(w.x), wy = pk2(w.y), wz = pk2(w.z), ww = pk2(w.w);
                a01 = ffma2(wx, d2l(za.x), a01); a23 = ffma2(wx, d2l(za.y), a23);
                a01 = ffma2(wy, d2l(zb.x), a01); a23 = ffma2(wy, d2l(zb.y), a23);
                a01 = ffma2(wz, d2l(zc.x), a01); a23 = ffma2(wz, d2l(zc.y), a23);
                a01 = ffma2(ww, d2l(zd.x), a01); a23 = ffma2(ww, d2l(zd.y), a23);
            }
            float2 lo = upk2(a01), hi = upk2(a23);
            float h0 = ftanh_(lo.x), h1 = ftanh_(lo.y), h2 = ftanh_(hi.x), h3 = ftanh_(hi.y);
            *(float4*)&h_s[tid * GQ] = make_float4(h0, h1, h2, h3);
            h_t[0 * HTS + tid] = h0; h_t[1 * HTS + tid] = h1;
            h_t[2 * HTS + tid] = h2; h_t[3 * HTS + tid] = h3;
        }
        __syncthreads();

        // ---- P2: head matvecs (packed f32x2) + fused activations ----
        if (tid < 92) {
            const double2* h2 = (const double2*)h_s;
            ull a01 = pk2(bsv), a23 = a01;
            #pragma unroll 5
            for (int jb = 0; jb < 25; jb++) {
                float4 w = Wp4[jb * od];
                double2 ha = h2[4*jb+0], hb = h2[4*jb+1], hc = h2[4*jb+2], hd = h2[4*jb+3];
                ull wx = pk2(w.x), wy = pk2(w.y), wz = pk2(w.z), ww = pk2(w.w);
                a01 = ffma2(wx, d2l(ha.x), a01); a23 = ffma2(wx, d2l(ha.y), a23);
                a01 = ffma2(wy, d2l(hb.x), a01); a23 = ffma2(wy, d2l(hb.y), a23);
                a01 = ffma2(wz, d2l(hc.x), a01); a23 = ffma2(wz, d2l(hc.y), a23);
                a01 = ffma2(ww, d2l(hd.x), a01); a23 = ffma2(ww, d2l(hd.y), a23);
            }
            float2 lo = upk2(a01), hi = upk2(a23);
            p_s[0 * PBLK + st] = apply_act(at, lo.x);
            p_s[1 * PBLK + st] = apply_act(at, lo.y);
            p_s[2 * PBLK + st] = apply_act(at, hi.x);
            p_s[3 * PBLK + st] = apply_act(at, hi.y);
        }
        __syncthreads();

        // ======== warp-local phases (batch g) ========
        float4 srv = *(const float4*)(pg + 20);
        float4 bv  = *(const float4*)(pg + 24);
        float4 swv = *(const float4*)(pg + 28);
        float sr_i = __fdividef(1.f, srv.x + srv.y + srv.z);
        float s_r0 = srv.x * sr_i, s_r1 = srv.y * sr_i, s_r2 = srv.z * sr_i;
        float sw_i = __fdividef(1.f, swv.x + swv.y + swv.z);
        float s_w0 = swv.x * sw_i, s_w1 = swv.y * sw_i, s_w2 = swv.z * sw_i;

        // ---- C1: content addressing, 4 rows, both heads ----
        float dr[4] = {0,0,0,0}, dw[4] = {0,0,0,0}, n2[4] = {0,0,0,0};
        float kr2 = 0.f, kw2 = 0.f;
        #pragma unroll
        for (int c = 0; c < 5; c++) {
            float4 krc = ((const float4*)pg)[c];
            float4 kwc = ((const float4*)(pg + 32))[c];
            kr2 = fmaf(krc.x,krc.x, fmaf(krc.y,krc.y, fmaf(krc.z,krc.z, fmaf(krc.w,krc.w, kr2))));
            kw2 = fmaf(kwc.x,kwc.x, fmaf(kwc.y,kwc.y, fmaf(kwc.z,kwc.z, fmaf(kwc.w,kwc.w, kw2))));
            #pragma unroll
            for (int i = 0; i < 4; i++) {
                float4 m = *(const float4*)&M_s[(g * NQ + lane + 32 * i) * VQ + c * 4];
                dr[i] = fmaf(krc.x,m.x, fmaf(krc.y,m.y, fmaf(krc.z,m.z, fmaf(krc.w,m.w, dr[i]))));
                dw[i] = fmaf(kwc.x,m.x, fmaf(kwc.y,m.y, fmaf(kwc.z,m.z, fmaf(kwc.w,m.w, dw[i]))));
                n2[i] = fmaf(m.x,m.x, fmaf(m.y,m.y, fmaf(m.z,m.z, fmaf(m.w,m.w, n2[i]))));
            }
        }
        float knr = sqrtf(kr2), knw = sqrtf(kw2);
        float er_r[4], ew_r[4], ser = 0.f, sew = 0.f;
        #pragma unroll
        for (int i = 0; i < 4; i++) {
            float mn = sqrtf(n2[i]);
            er_r[i] = __expf(bv.x * __fdividef(dr[i], knr * mn + EPSQ));
            ew_r[i] = __expf(bv.z * __fdividef(dw[i], knw * mn + EPSQ));
            ser += er_r[i]; sew += ew_r[i];
        }
        ser = warp_sum(ser); sew = warp_sum(sew);

        // ---- C2: read-head interp + conv via shfl + sharpen ----
        float ginv = bv.y * __fdividef(1.f, ser);
        float omg  = 1.f - bv.y;
        float wg_r[4];
        #pragma unroll
        for (int i = 0; i < 4; i++)
            wg_r[i] = fmaf(ginv, er_r[i], omg * wprev_r[i]);
        float wpr_r[4], ssp = 0.f;
        #pragma unroll
        for (int i = 0; i < 4; i++) {
            float tnp = (lane == 0)  ? wg_r[(i + 1) & 3] : wg_r[i];
            float tnm = (lane == 31) ? wg_r[(i + 3) & 3] : wg_r[i];
            float w_p = __shfl_sync(0xffffffffu, tnp, (lane + 1)  & 31);
            float w_m = __shfl_sync(0xffffffffu, tnm, (lane + 31) & 31);
            float ws  = s_r0 * w_p + s_r1 * wg_r[i] + s_r2 * w_m;
            wpr_r[i]  = __expf(srv.w * __logf(ws));
            ssp += wpr_r[i];
        }
        float sp = warp_sum(ssp);
        float invsp = __fdividef(1.f, sp + EPSQ);

        // ---- C3: write-head interp + conv via shfl + sharpen ----
        float gwinv = bv.w * __fdividef(1.f, sew);
        float omgsp = (1.f - bv.w) * invsp;
        float wt_r[4];
        #pragma unroll
        for (int i = 0; i < 4; i++)
            wt_r[i] = fmaf(gwinv, ew_r[i], omgsp * wpr_r[i]);
        float wpw_r[4], swp = 0.f;
        #pragma unroll
        for (int i = 0; i < 4; i++) {
            float tnp = (lane == 0)  ? wt_r[(i + 1) & 3] : wt_r[i];
            float tnm = (lane == 31) ? wt_r[(i + 3) & 3] : wt_r[i];
            float w_p = __shfl_sync(0xffffffffu, tnp, (lane + 1)  & 31);
            float w_m = __shfl_sync(0xffffffffu, tnm, (lane + 31) & 31);
            float ws  = s_w0 * w_p + s_w1 * wt_r[i] + s_w2 * w_m;
            wpw_r[i]  = __expf(swv.w * __logf(ws));
            swp += wpw_r[i];
        }
        float spw = warp_sum(swp);
        float invspw = __fdividef(1.f, spw + EPSQ);
        #pragma unroll
        for (int i = 0; i < 4; i++)
            wprev_r[i] = wpw_r[i] * invspw;

        // ---- C4: fused r-readout + M update (packed f32x2) ----
        ull wr_d[4], ww_d[4], nww_d[4];
        #pragma unroll
        for (int i = 0; i < 4; i++) {
            wr_d[i]  = pk2(wpr_r[i] * invsp);
            ww_d[i]  = pk2(wprev_r[i]);
            nww_d[i] = pk2(-wprev_r[i]);
        }
        ull r01[5], r23[5];
        #pragma unroll
        for (int c = 0; c < 5; c++) {
            double2 ed = ((const double2*)(pg + 52))[c];
            double2 ad = ((const double2*)(pg + 72))[c];
            ull e01 = d2l(ed.x), e23 = d2l(ed.y);
            ull a01 = d2l(ad.x), a23 = d2l(ad.y);
            ull acc01 = 0ull, acc23 = 0ull;
            #pragma unroll
            for (int i = 0; i < 4; i++) {
                double2* mp = (double2*)&M_s[(g * NQ + lane + 32 * i) * VQ + c * 4];
                double2 md = *mp;
                ull m01 = d2l(md.x), m23 = d2l(md.y);
                acc01 = ffma2(wr_d[i], m01, acc01);
                acc23 = ffma2(wr_d[i], m23, acc23);
                ull nwe01 = fmul2(nww_d[i], e01), nwe23 = fmul2(nww_d[i], e23);
                m01 = ffma2(nwe01, m01, m01);  m23 = ffma2(nwe23, m23, m23);
                m01 = ffma2(ww_d[i], a01, m01); m23 = ffma2(ww_d[i], a23, m23);
                md.x = l2d(m01); md.y = l2d(m23);
                *mp = md;
            }
            r01[c] = warp_sum2(acc01);
            r23[c] = warp_sum2(acc23);
        }
        if (lane == 0) {
            #pragma unroll
            for (int c = 0; c < 5; c++) {
                float2 x01 = upk2(r01[c]), x23 = upk2(r23[c]);
                int v = c * 4;
                z_s[(IQ + v + 0) * GQ + g] = x01.x;
                z_s[(IQ + v + 1) * GQ + g] = x01.y;
                z_s[(IQ + v + 2) * GQ + g] = x23.x;
                z_s[(IQ + v + 3) * GQ + g] = x23.y;
                *(float4*)&h_t[g * HTS + 100 + v] =
                    make_float4(x01.x, x01.y, x23.x, x23.y);
            }
        }
        __syncwarp();

        // ---- out = sigmoid([h, r] @ Wf + bf)  (8 outs x 4 partials of 8 jb) ----
        {
            int o = lane & 7, part = lane >> 3;
            const float4* wv  = (const float4*)Wf4_g + o;        // + jb*8
            const float4* hv4 = (const float4*)(h_t + g * HTS);  // + jb
            float acc = 0.f;
            #pragma unroll
            for (int jl = 0; jl < 8; jl++) {
                int jb = part * 8 + jl;
                float4 w = wv[jb * OQ];
                float4 h = hv4[jb];
                acc = fmaf(w.x, h.x, fmaf(w.y, h.y, fmaf(w.z, h.z, fmaf(w.w, h.w, acc))));
            }
            acc += __shfl_xor_sync(0xffffffffu, acc, 8);
            acc += __shfl_xor_sync(0xffffffffu, acc, 16);
            if (lane < 8)
                out[((b0 + g) * TQ + t) * OQ + o] = fsigmoid_(acc + bfv);
        }
        // prefetch next x_t
        if (t + 1 < TQ && tid < IQ * GQ) {
            int gg = tid / IQ, i = tid - gg * IQ;
            z_s[i * GQ + gg] = x[((b0 + gg) * TQ + (t + 1)) * IQ + i];
        }
        __syncthreads();
    }
}

extern "C" void kernel_launch(void* const* d_in, const int* in_sizes, int n_in,
                              void* d_out, int out_size) {
    const float* x      = (const float*)d_in[0];
    const float* Wc     = (const float*)d_in[1];
    const float* bc     = (const float*)d_in[2];
    const float* Wr     = (const float*)d_in[3];
    const float* br     = (const float*)d_in[4];
    const float* Ww     = (const float*)d_in[5];
    const float* bw     = (const float*)d_in[6];
    const float* Wf     = (const float*)d_in[7];
    const float* bf     = (const float*)d_in[8];
    const float* r_bias = (const float*)d_in[9];
    const float* M_bias = (const float*)d_in[10];

    int B = in_sizes[0] / (TQ * IQ);        // 2048
    int grid = B / GQ;                      // 512

    prep_kernel<<<65, 256>>>(Wc, Wr, Ww, Wf);   // 16496 elements

    size_t smem = (size_t)(GQ * NQ * VQ + 32 * GQ + CQ * GQ + GQ * PBLK + GQ * HTS)
                  * sizeof(float);          // 46656 B
    cudaFuncSetAttribute(ntm_kernel, cudaFuncAttributeMaxDynamicSharedMemorySize, (int)smem);

    ntm_kernel<<<grid, BLK, smem>>>(x, bc, br, bw, bf, r_bias, M_bias, (float*)d_out);
}